// round 15
// baseline (speedup 1.0000x reference)
#include <cuda_runtime.h>
#include <cuda_fp16.h>
#include <mma.h>
#include <math_constants.h>
#include <cstdint>

using namespace nvcuda;

#define DD   128
#define MAXN 50048
#define MAXE 1600256

// ---------------- device scratch (no allocations allowed) ----------------
// KV interleaved: row = 256 floats = [K(128) | V(128)], 1024 B stride.
__device__ __align__(128) float  g_KV[MAXN * 256];
__device__ __align__(128) float  g_Q [MAXN * DD];
__device__ __align__(128) __half g_Whi[3 * DD * DD];
__device__ __align__(128) __half g_Wlo[3 * DD * DD];
__device__ int g_deg[MAXN];
__device__ int g_off[MAXN + 1];
__device__ int g_pos[MAXN];
__device__ int g_esrc[MAXE];        // BYTE offsets into g_KV (src * 1024)
__device__ int g_chain[64];

// ---------------- prep: split W hi/lo + zero g_deg + chain flags ------------
__global__ void prep_w(const float* __restrict__ Wk,
                       const float* __restrict__ Wq,
                       const float* __restrict__ Wv, int n) {
    int idx = blockIdx.x * blockDim.x + threadIdx.x;
    if (idx < 64) g_chain[idx] = 0;
    if (idx < n) g_deg[idx] = 0;
    if (idx >= 3 * DD * DD) return;
    int which = idx / (DD * DD);
    int i     = idx - which * (DD * DD);
    const float* W = (which == 0) ? Wk : (which == 1) ? Wq : Wv;
    float v  = W[i];
    __half h = __float2half_rn(v);
    __half l = __float2half_rn(v - __half2float(h));
    g_Whi[idx] = h;
    g_Wlo[idx] = l;
}

// ---------------- projection via wmma, 2 CTAs/SM (unchanged r14) ------------
#define LDH  136
#define LDO  132
#define SA_BYTES  (64 * LDH * 2)
#define SB_BYTES  (128 * LDH * 2)
#define PS_AHI    0
#define PS_ALO    (SA_BYTES)
#define PS_BHI    (2 * SA_BYTES)
#define PS_BLO    (2 * SA_BYTES + SB_BYTES)
#define PS_TOT    (2 * SA_BYTES + 2 * SB_BYTES)

__global__ void __launch_bounds__(256, 2)
proj_wmma(const float* __restrict__ X,
          const float* __restrict__ bk,
          const float* __restrict__ bq,
          const float* __restrict__ bv,
          int n) {
    extern __shared__ char smem[];
    __half* sAhi = (__half*)(smem + PS_AHI);
    __half* sAlo = (__half*)(smem + PS_ALO);
    __half* sBhi = (__half*)(smem + PS_BHI);
    __half* sBlo = (__half*)(smem + PS_BLO);
    float*  sOut = (float*)(smem);

    const int tid = threadIdx.x, wid = tid >> 5;
    const int wr = wid >> 2, wc = wid & 3;
    const int which = blockIdx.y;
    const int m0 = blockIdx.x * 64;

    for (int idx = tid; idx < 64 * 32; idx += 256) {
        int row = idx >> 5;
        int c0  = (idx & 31) << 2;
        int gr  = m0 + row;
        float4 v = (gr < n) ? *(const float4*)&X[(long)gr * DD + c0]
                            : make_float4(0.f, 0.f, 0.f, 0.f);
        __half h0 = __float2half_rn(v.x), h1 = __float2half_rn(v.y);
        __half h2 = __float2half_rn(v.z), h3 = __float2half_rn(v.w);
        __half l0 = __float2half_rn(v.x - __half2float(h0));
        __half l1 = __float2half_rn(v.y - __half2float(h1));
        __half l2 = __float2half_rn(v.z - __half2float(h2));
        __half l3 = __float2half_rn(v.w - __half2float(h3));
        __half2 H01 = __halves2half2(h0, h1), H23 = __halves2half2(h2, h3);
        __half2 L01 = __halves2half2(l0, l1), L23 = __halves2half2(l2, l3);
        uint2 uh; uh.x = *(uint32_t*)&H01; uh.y = *(uint32_t*)&H23;
        uint2 ul; ul.x = *(uint32_t*)&L01; ul.y = *(uint32_t*)&L23;
        *(uint2*)&sAhi[row * LDH + c0] = uh;
        *(uint2*)&sAlo[row * LDH + c0] = ul;
    }

    {
        const uint4* ghi = (const uint4*)(g_Whi + which * (DD * DD));
        const uint4* glo = (const uint4*)(g_Wlo + which * (DD * DD));
        for (int idx = tid; idx < 128 * 16; idx += 256) {
            int c  = idx >> 4;
            int kq = (idx & 15) << 3;
            uint4 vh = ghi[idx];
            uint4 vl = glo[idx];
            *(uint4*)&sBhi[c * LDH + kq] = vh;
            *(uint4*)&sBlo[c * LDH + kq] = vl;
        }
    }
    __syncthreads();

    wmma::fragment<wmma::accumulator, 16, 16, 16, float> acc[2][2];
#pragma unroll
    for (int i = 0; i < 2; i++)
#pragma unroll
        for (int j = 0; j < 2; j++) wmma::fill_fragment(acc[i][j], 0.f);

#pragma unroll
    for (int k0 = 0; k0 < 128; k0 += 16) {
        wmma::fragment<wmma::matrix_a, 16, 16, 16, __half, wmma::row_major> ah[2], al[2];
#pragma unroll
        for (int i = 0; i < 2; i++) {
            wmma::load_matrix_sync(ah[i], sAhi + (wr * 32 + i * 16) * LDH + k0, LDH);
            wmma::load_matrix_sync(al[i], sAlo + (wr * 32 + i * 16) * LDH + k0, LDH);
        }
#pragma unroll
        for (int j = 0; j < 2; j++) {
            wmma::fragment<wmma::matrix_b, 16, 16, 16, __half, wmma::col_major> bh, bl;
            wmma::load_matrix_sync(bh, sBhi + (wc * 32 + j * 16) * LDH + k0, LDH);
            wmma::load_matrix_sync(bl, sBlo + (wc * 32 + j * 16) * LDH + k0, LDH);
#pragma unroll
            for (int i = 0; i < 2; i++) {
                wmma::mma_sync(acc[i][j], ah[i], bh, acc[i][j]);
                wmma::mma_sync(acc[i][j], ah[i], bl, acc[i][j]);
                wmma::mma_sync(acc[i][j], al[i], bh, acc[i][j]);
            }
        }
    }

    __syncthreads();
#pragma unroll
    for (int i = 0; i < 2; i++)
#pragma unroll
        for (int j = 0; j < 2; j++)
            wmma::store_matrix_sync(&sOut[(wr * 32 + i * 16) * LDO + wc * 32 + j * 16],
                                    acc[i][j], LDO, wmma::mem_row_major);
    __syncthreads();

    const float* b = (which == 0) ? bk : (which == 1) ? bq : bv;
    for (int idx = tid; idx < 64 * 32; idx += 256) {
        int row = idx >> 5;
        int c0  = (idx & 31) << 2;
        int gr  = m0 + row;
        if (gr < n) {
            float4 o  = *(const float4*)&sOut[row * LDO + c0];
            float4 bb = *(const float4*)&b[c0];
            o.x += bb.x; o.y += bb.y; o.z += bb.z; o.w += bb.w;
            if (which == 0)      *(float4*)&g_KV[(long)gr * 256 + c0]       = o;
            else if (which == 2) *(float4*)&g_KV[(long)gr * 256 + 128 + c0] = o;
            else                 *(float4*)&g_Q [(long)gr * DD + c0]        = o;
        }
    }
}

// ---------------- CSR build (unchanged) --------------------------------------
__global__ void hist_kernel(const int* __restrict__ dst, int E) {
    int base = blockIdx.x * 1024 + threadIdx.x;
#pragma unroll
    for (int i = 0; i < 4; i++) {
        int e = base + i * 256;
        if (e < E) atomicAdd(&g_deg[dst[e]], 1);
    }
}

__global__ void __launch_bounds__(1024, 1)
scan_chain_kernel(int n) {
    __shared__ int wsum[32];
    __shared__ int s_total, s_prefix;

    const int tid  = threadIdx.x;
    const int lane = tid & 31, warp = tid >> 5;
    const int i    = blockIdx.x * 1024 + tid;

    int v = (i < n) ? g_deg[i] : 0;

    int inc = v;
#pragma unroll
    for (int o = 1; o < 32; o <<= 1) {
        int t = __shfl_up_sync(0xffffffffu, inc, o);
        if (lane >= o) inc += t;
    }
    if (lane == 31) wsum[warp] = inc;
    __syncthreads();

    if (warp == 0) {
        int w  = wsum[lane];
        int wi = w;
#pragma unroll
        for (int o = 1; o < 32; o <<= 1) {
            int t = __shfl_up_sync(0xffffffffu, wi, o);
            if (lane >= o) wi += t;
        }
        wsum[lane] = wi - w;
        if (lane == 31) s_total = wi;
    }
    __syncthreads();

    const int excl = (inc - v) + wsum[warp];

    if (tid == 0) {
        int prefix = 0;
        if (blockIdx.x > 0) {
            int f;
            do { f = atomicAdd(&g_chain[blockIdx.x - 1], 0); } while (f == 0);
            prefix = f - 1;
        }
        atomicExch(&g_chain[blockIdx.x], prefix + s_total + 1);
        s_prefix = prefix;
    }
    __syncthreads();

    if (i < n) {
        int o = s_prefix + excl;
        g_off[i] = o;
        g_pos[i] = o;
    }
    if (blockIdx.x == gridDim.x - 1 && tid == 0)
        g_off[n] = s_prefix + s_total;
}

__global__ void fill_kernel(const int* __restrict__ src,
                            const int* __restrict__ dst, int E) {
    int base = blockIdx.x * 1024 + threadIdx.x;
#pragma unroll
    for (int i = 0; i < 4; i++) {
        int e = base + i * 256;
        if (e < E) {
            int p = atomicAdd(&g_pos[dst[e]], 1);
            g_esrc[p] = src[e] << 10;     // byte offset into g_KV
        }
    }
}

// ---------------- fused edge-softmax + aggregate: half-warp edge pairing -----
// Warp = one dst node, processes 2 edges/step: lanes 0-15 edge A, 16-31 edge B.
// Lane owns 8 output dims (2 float4); head = (lane&15)>>2; head-reduce = 2
// butterfly SHFLs over a 4-lane group (shared by both edges). Cross-half
// combine once at the end.
__global__ void __launch_bounds__(256, 6)
aggregate_kernel(float* __restrict__ out, int n) {
    int gw   = (blockIdx.x * blockDim.x + threadIdx.x) >> 5;
    int lane = threadIdx.x & 31;
    if (gw >= n) return;

    const int half = lane >> 4;          // which edge of the pair
    const int hl   = lane & 15;          // lane within half: dims [hl*8, hl*8+8)

    const int beg = g_off[gw];
    const int end = g_off[gw + 1];

    const char* KVb = (const char*)g_KV + hl * 32;
    const float4 q0 = *(const float4*)&g_Q[(long)gw * DD + hl * 8];
    const float4 q1 = *(const float4*)&g_Q[(long)gw * DD + hl * 8 + 4];

    float  d = 0.f;
    float4 a0 = make_float4(0.f, 0.f, 0.f, 0.f);
    float4 a1 = make_float4(0.f, 0.f, 0.f, 0.f);

    for (int e0 = beg; e0 < end; e0 += 32) {
        int myoff = (e0 + lane < end) ? g_esrc[e0 + lane] : 0;
        int cnt   = min(32, end - e0);
        int fullp = cnt & ~7;

        int b = 0;
        for (; b < fullp; b += 8) {
#pragma unroll
            for (int jj = 0; jj < 8; jj += 2) {
                int off = __shfl_sync(0xffffffffu, myoff, b + jj + half);
                const float4 k0 = *(const float4*)(KVb + off);
                const float4 k1 = *(const float4*)(KVb + off + 16);
                float sc = k0.x*q0.x + k0.y*q0.y + k0.z*q0.z + k0.w*q0.w
                         + k1.x*q1.x + k1.y*q1.y + k1.z*q1.z + k1.w*q1.w;
                sc += __shfl_xor_sync(0xffffffffu, sc, 1);
                sc += __shfl_xor_sync(0xffffffffu, sc, 2);
                float p = __expf(sc);
                const float4 v0 = *(const float4*)(KVb + off + 512);
                const float4 v1 = *(const float4*)(KVb + off + 528);
                d += p;
                a0.x = fmaf(p, v0.x, a0.x); a0.y = fmaf(p, v0.y, a0.y);
                a0.z = fmaf(p, v0.z, a0.z); a0.w = fmaf(p, v0.w, a0.w);
                a1.x = fmaf(p, v1.x, a1.x); a1.y = fmaf(p, v1.y, a1.y);
                a1.z = fmaf(p, v1.z, a1.z); a1.w = fmaf(p, v1.w, a1.w);
            }
        }
        for (; b < cnt; b += 2) {
            int j   = b + half;
            int sl  = min(j, cnt - 1);
            int off = __shfl_sync(0xffffffffu, myoff, sl);
            const float4 k0 = *(const float4*)(KVb + off);
            const float4 k1 = *(const float4*)(KVb + off + 16);
            float sc = k0.x*q0.x + k0.y*q0.y + k0.z*q0.z + k0.w*q0.w
                     + k1.x*q1.x + k1.y*q1.y + k1.z*q1.z + k1.w*q1.w;
            sc += __shfl_xor_sync(0xffffffffu, sc, 1);
            sc += __shfl_xor_sync(0xffffffffu, sc, 2);
            float p = __expf(sc);
            p = (j < cnt) ? p : 0.f;
            const float4 v0 = *(const float4*)(KVb + off + 512);
            const float4 v1 = *(const float4*)(KVb + off + 528);
            d += p;
            a0.x = fmaf(p, v0.x, a0.x); a0.y = fmaf(p, v0.y, a0.y);
            a0.z = fmaf(p, v0.z, a0.z); a0.w = fmaf(p, v0.w, a0.w);
            a1.x = fmaf(p, v1.x, a1.x); a1.y = fmaf(p, v1.y, a1.y);
            a1.z = fmaf(p, v1.z, a1.z); a1.w = fmaf(p, v1.w, a1.w);
        }
    }

    // combine halves (lanes 0-15 pick up lanes 16-31's partials)
    d    += __shfl_down_sync(0xffffffffu, d,    16);
    a0.x += __shfl_down_sync(0xffffffffu, a0.x, 16);
    a0.y += __shfl_down_sync(0xffffffffu, a0.y, 16);
    a0.z += __shfl_down_sync(0xffffffffu, a0.z, 16);
    a0.w += __shfl_down_sync(0xffffffffu, a0.w, 16);
    a1.x += __shfl_down_sync(0xffffffffu, a1.x, 16);
    a1.y += __shfl_down_sync(0xffffffffu, a1.y, 16);
    a1.z += __shfl_down_sync(0xffffffffu, a1.z, 16);
    a1.w += __shfl_down_sync(0xffffffffu, a1.w, 16);

    if (half == 0) {
        float inv = (d > 0.f) ? (1.f / d) : 0.f;
        float4 o0 = make_float4(a0.x * inv, a0.y * inv, a0.z * inv, a0.w * inv);
        float4 o1 = make_float4(a1.x * inv, a1.y * inv, a1.z * inv, a1.w * inv);
        *(float4*)&out[(long)gw * DD + hl * 8]     = o0;
        *(float4*)&out[(long)gw * DD + hl * 8 + 4] = o1;
    }
}

// ---------------- launch: fork-join overlap of proj with CSR chain ----------
extern "C" void kernel_launch(void* const* d_in, const int* in_sizes, int n_in,
                              void* d_out, int out_size) {
    const float* x  = (const float*)d_in[0];
    const float* Wk = (const float*)d_in[1];
    const float* bk = (const float*)d_in[2];
    const float* Wq = (const float*)d_in[3];
    const float* bq = (const float*)d_in[4];
    const float* Wv = (const float*)d_in[5];
    const float* bv = (const float*)d_in[6];
    const int*  src = (const int*)d_in[7];
    const int*  dst = (const int*)d_in[8];
    float* out = (float*)d_out;

    int n = in_sizes[0] / DD;   // 50000
    int E = in_sizes[7];        // 1600000

    cudaStream_t s2;
    cudaStreamCreateWithFlags(&s2, cudaStreamNonBlocking);
    cudaEvent_t evF, evJ;
    cudaEventCreateWithFlags(&evF, cudaEventDisableTiming);
    cudaEventCreateWithFlags(&evJ, cudaEventDisableTiming);

    cudaFuncSetAttribute(proj_wmma, cudaFuncAttributeMaxDynamicSharedMemorySize,
                         PS_TOT);

    int prepN = (n > 3 * DD * DD) ? n : 3 * DD * DD;
    prep_w<<<(prepN + 255) / 256, 256>>>(Wk, Wq, Wv, n);     // stream 0

    // fork: proj on s2 (needs prep's W split); CSR chain stays on stream 0
    cudaEventRecord(evF, 0);
    cudaStreamWaitEvent(s2, evF, 0);
    dim3 pg((n + 63) / 64, 3);
    proj_wmma<<<pg, 256, PS_TOT, s2>>>(x, bk, bq, bv, n);

    hist_kernel<<<(E + 1023) / 1024, 256>>>(dst, E);
    scan_chain_kernel<<<(n + 1023) / 1024, 1024>>>(n);
    fill_kernel<<<(E + 1023) / 1024, 256>>>(src, dst, E);

    // join: aggregate needs both branches
    cudaEventRecord(evJ, s2);
    cudaStreamWaitEvent(0, evJ, 0);

    int totalThreads = n * 32;
    aggregate_kernel<<<(totalThreads + 255) / 256, 256>>>(out, n);
}

// round 16
// speedup vs baseline: 1.1593x; 1.1593x over previous
#include <cuda_runtime.h>
#include <cuda_fp16.h>
#include <mma.h>
#include <math_constants.h>
#include <cstdint>

using namespace nvcuda;

#define DD   128
#define MAXN 50048
#define MAXE 1600256

// ---------------- device scratch (no allocations allowed) ----------------
__device__ __align__(128) float  g_K [MAXN * DD];
__device__ __align__(128) float  g_Q [MAXN * DD];
__device__ __align__(128) __half g_Vh[MAXN * DD];
__device__ __align__(128) __half g_Whi[3 * DD * DD];
__device__ __align__(128) __half g_Wlo[3 * DD * DD];
__device__ int g_deg[MAXN];
__device__ int g_off[MAXN + 1];
__device__ int g_pos[MAXN];
__device__ int g_esrc[MAXE];        // BYTE offsets into g_K (src * 512)
__device__ int g_chain[64];

// ---------------- prep: split W hi/lo + zero g_deg + chain flags ------------
__global__ void prep_w(const float* __restrict__ Wk,
                       const float* __restrict__ Wq,
                       const float* __restrict__ Wv, int n) {
    int idx = blockIdx.x * blockDim.x + threadIdx.x;
    if (idx < 64) g_chain[idx] = 0;
    if (idx < n) g_deg[idx] = 0;
    if (idx >= 3 * DD * DD) return;
    int which = idx / (DD * DD);
    int i     = idx - which * (DD * DD);
    const float* W = (which == 0) ? Wk : (which == 1) ? Wq : Wv;
    float v  = W[i];
    __half h = __float2half_rn(v);
    __half l = __float2half_rn(v - __half2float(h));
    g_Whi[idx] = h;
    g_Wlo[idx] = l;
}

// ---------------- projection via wmma, 2 CTAs/SM (r13) ----------------------
#define LDH  136
#define LDO  132
#define SA_BYTES  (64 * LDH * 2)
#define SB_BYTES  (128 * LDH * 2)
#define PS_AHI    0
#define PS_ALO    (SA_BYTES)
#define PS_BHI    (2 * SA_BYTES)
#define PS_BLO    (2 * SA_BYTES + SB_BYTES)
#define PS_TOT    (2 * SA_BYTES + 2 * SB_BYTES)

__global__ void __launch_bounds__(256, 2)
proj_wmma(const float* __restrict__ X,
          const float* __restrict__ bk,
          const float* __restrict__ bq,
          const float* __restrict__ bv,
          int n) {
    extern __shared__ char smem[];
    __half* sAhi = (__half*)(smem + PS_AHI);
    __half* sAlo = (__half*)(smem + PS_ALO);
    __half* sBhi = (__half*)(smem + PS_BHI);
    __half* sBlo = (__half*)(smem + PS_BLO);
    float*  sOut = (float*)(smem);

    const int tid = threadIdx.x, wid = tid >> 5;
    const int wr = wid >> 2, wc = wid & 3;
    const int which = blockIdx.y;
    const int m0 = blockIdx.x * 64;

    for (int idx = tid; idx < 64 * 32; idx += 256) {
        int row = idx >> 5;
        int c0  = (idx & 31) << 2;
        int gr  = m0 + row;
        float4 v = (gr < n) ? *(const float4*)&X[(long)gr * DD + c0]
                            : make_float4(0.f, 0.f, 0.f, 0.f);
        __half h0 = __float2half_rn(v.x), h1 = __float2half_rn(v.y);
        __half h2 = __float2half_rn(v.z), h3 = __float2half_rn(v.w);
        __half l0 = __float2half_rn(v.x - __half2float(h0));
        __half l1 = __float2half_rn(v.y - __half2float(h1));
        __half l2 = __float2half_rn(v.z - __half2float(h2));
        __half l3 = __float2half_rn(v.w - __half2float(h3));
        __half2 H01 = __halves2half2(h0, h1), H23 = __halves2half2(h2, h3);
        __half2 L01 = __halves2half2(l0, l1), L23 = __halves2half2(l2, l3);
        uint2 uh; uh.x = *(uint32_t*)&H01; uh.y = *(uint32_t*)&H23;
        uint2 ul; ul.x = *(uint32_t*)&L01; ul.y = *(uint32_t*)&L23;
        *(uint2*)&sAhi[row * LDH + c0] = uh;
        *(uint2*)&sAlo[row * LDH + c0] = ul;
    }

    {
        const uint4* ghi = (const uint4*)(g_Whi + which * (DD * DD));
        const uint4* glo = (const uint4*)(g_Wlo + which * (DD * DD));
        for (int idx = tid; idx < 128 * 16; idx += 256) {
            int c  = idx >> 4;
            int kq = (idx & 15) << 3;
            uint4 vh = ghi[idx];
            uint4 vl = glo[idx];
            *(uint4*)&sBhi[c * LDH + kq] = vh;
            *(uint4*)&sBlo[c * LDH + kq] = vl;
        }
    }
    __syncthreads();

    wmma::fragment<wmma::accumulator, 16, 16, 16, float> acc[2][2];
#pragma unroll
    for (int i = 0; i < 2; i++)
#pragma unroll
        for (int j = 0; j < 2; j++) wmma::fill_fragment(acc[i][j], 0.f);

#pragma unroll
    for (int k0 = 0; k0 < 128; k0 += 16) {
        wmma::fragment<wmma::matrix_a, 16, 16, 16, __half, wmma::row_major> ah[2], al[2];
#pragma unroll
        for (int i = 0; i < 2; i++) {
            wmma::load_matrix_sync(ah[i], sAhi + (wr * 32 + i * 16) * LDH + k0, LDH);
            wmma::load_matrix_sync(al[i], sAlo + (wr * 32 + i * 16) * LDH + k0, LDH);
        }
#pragma unroll
        for (int j = 0; j < 2; j++) {
            wmma::fragment<wmma::matrix_b, 16, 16, 16, __half, wmma::col_major> bh, bl;
            wmma::load_matrix_sync(bh, sBhi + (wc * 32 + j * 16) * LDH + k0, LDH);
            wmma::load_matrix_sync(bl, sBlo + (wc * 32 + j * 16) * LDH + k0, LDH);
#pragma unroll
            for (int i = 0; i < 2; i++) {
                wmma::mma_sync(acc[i][j], ah[i], bh, acc[i][j]);
                wmma::mma_sync(acc[i][j], ah[i], bl, acc[i][j]);
                wmma::mma_sync(acc[i][j], al[i], bh, acc[i][j]);
            }
        }
    }

    __syncthreads();
#pragma unroll
    for (int i = 0; i < 2; i++)
#pragma unroll
        for (int j = 0; j < 2; j++)
            wmma::store_matrix_sync(&sOut[(wr * 32 + i * 16) * LDO + wc * 32 + j * 16],
                                    acc[i][j], LDO, wmma::mem_row_major);
    __syncthreads();

    const float* b = (which == 0) ? bk : (which == 1) ? bq : bv;
    for (int idx = tid; idx < 64 * 32; idx += 256) {
        int row = idx >> 5;
        int c0  = (idx & 31) << 2;
        int gr  = m0 + row;
        if (gr < n) {
            float4 o  = *(const float4*)&sOut[row * LDO + c0];
            float4 bb = *(const float4*)&b[c0];
            o.x += bb.x; o.y += bb.y; o.z += bb.z; o.w += bb.w;
            if (which == 2) {
                __half2 h01 = __halves2half2(__float2half_rn(o.x), __float2half_rn(o.y));
                __half2 h23 = __halves2half2(__float2half_rn(o.z), __float2half_rn(o.w));
                uint2 u; u.x = *(uint32_t*)&h01; u.y = *(uint32_t*)&h23;
                *(uint2*)&g_Vh[(long)gr * DD + c0] = u;
            } else {
                float* __restrict__ Y = (which == 0) ? g_K : g_Q;
                *(float4*)&Y[(long)gr * DD + c0] = o;
            }
        }
    }
}

// ---------------- CSR build (r13) --------------------------------------------
__global__ void hist_kernel(const int* __restrict__ dst, int E) {
    int base = blockIdx.x * 1024 + threadIdx.x;
#pragma unroll
    for (int i = 0; i < 4; i++) {
        int e = base + i * 256;
        if (e < E) atomicAdd(&g_deg[dst[e]], 1);
    }
}

__global__ void __launch_bounds__(1024, 1)
scan_chain_kernel(int n) {
    __shared__ int wsum[32];
    __shared__ int s_total, s_prefix;

    const int tid  = threadIdx.x;
    const int lane = tid & 31, warp = tid >> 5;
    const int i    = blockIdx.x * 1024 + tid;

    int v = (i < n) ? g_deg[i] : 0;

    int inc = v;
#pragma unroll
    for (int o = 1; o < 32; o <<= 1) {
        int t = __shfl_up_sync(0xffffffffu, inc, o);
        if (lane >= o) inc += t;
    }
    if (lane == 31) wsum[warp] = inc;
    __syncthreads();

    if (warp == 0) {
        int w  = wsum[lane];
        int wi = w;
#pragma unroll
        for (int o = 1; o < 32; o <<= 1) {
            int t = __shfl_up_sync(0xffffffffu, wi, o);
            if (lane >= o) wi += t;
        }
        wsum[lane] = wi - w;
        if (lane == 31) s_total = wi;
    }
    __syncthreads();

    const int excl = (inc - v) + wsum[warp];

    if (tid == 0) {
        int prefix = 0;
        if (blockIdx.x > 0) {
            int f;
            do { f = atomicAdd(&g_chain[blockIdx.x - 1], 0); } while (f == 0);
            prefix = f - 1;
        }
        atomicExch(&g_chain[blockIdx.x], prefix + s_total + 1);
        s_prefix = prefix;
    }
    __syncthreads();

    if (i < n) {
        int o = s_prefix + excl;
        g_off[i] = o;
        g_pos[i] = o;
    }
    if (blockIdx.x == gridDim.x - 1 && tid == 0)
        g_off[n] = s_prefix + s_total;
}

__global__ void fill_kernel(const int* __restrict__ src,
                            const int* __restrict__ dst, int E) {
    int base = blockIdx.x * 1024 + threadIdx.x;
#pragma unroll
    for (int i = 0; i < 4; i++) {
        int e = base + i * 256;
        if (e < E) {
            int p = atomicAdd(&g_pos[dst[e]], 1);
            g_esrc[p] = src[e] << 9;
        }
    }
}

// ---------------- fused edge-softmax + aggregate (r13 + cnt==32 fast path) --
__global__ void __launch_bounds__(256, 6)
aggregate_kernel(float* __restrict__ out, int n) {
    int gw   = (blockIdx.x * blockDim.x + threadIdx.x) >> 5;
    int lane = threadIdx.x & 31;
    if (gw >= n) return;

    const int beg = g_off[gw];
    const int end = g_off[gw + 1];

    const char* Kb = (const char*)g_K  + lane * 16;
    const char* Vb = (const char*)g_Vh + lane * 8;
    const float4 q4 = *(const float4*)&g_Q[(long)gw * DD + lane * 4];

    float  d = 0.f;
    float4 acc = make_float4(0.f, 0.f, 0.f, 0.f);

    for (int e0 = beg; e0 < end; e0 += 32) {
        if (end - e0 >= 32) {
            // full chunk: no predication anywhere
            int myoff = g_esrc[e0 + lane];
#pragma unroll
            for (int b = 0; b < 32; b += 8) {
#pragma unroll
                for (int j = 0; j < 8; j++) {
                    int off = __shfl_sync(0xffffffffu, myoff, b + j);
                    const float4 k4 = *(const float4*)(Kb + off);
                    float sc = k4.x * q4.x + k4.y * q4.y + k4.z * q4.z + k4.w * q4.w;
                    sc += __shfl_xor_sync(0xffffffffu, sc, 1);
                    sc += __shfl_xor_sync(0xffffffffu, sc, 2);
                    sc += __shfl_xor_sync(0xffffffffu, sc, 4);
                    float p = __expf(sc);
                    uint2 vraw = *(const uint2*)(Vb + (off >> 1));
                    float2 va = __half22float2(*reinterpret_cast<const __half2*>(&vraw.x));
                    float2 vb = __half22float2(*reinterpret_cast<const __half2*>(&vraw.y));
                    d += p;
                    acc.x = fmaf(p, va.x, acc.x);
                    acc.y = fmaf(p, va.y, acc.y);
                    acc.z = fmaf(p, vb.x, acc.z);
                    acc.w = fmaf(p, vb.y, acc.w);
                }
            }
        } else {
            // tail chunk: predicated
            int cnt   = end - e0;
            int myoff = (e0 + lane < end) ? g_esrc[e0 + lane] : 0;
            for (int b = 0; b < cnt; b += 8) {
#pragma unroll
                for (int j = 0; j < 8; j++) {
                    int off = __shfl_sync(0xffffffffu, myoff, b + j);
                    const float4 k4 = *(const float4*)(Kb + off);
                    float sc = k4.x * q4.x + k4.y * q4.y + k4.z * q4.z + k4.w * q4.w;
                    sc += __shfl_xor_sync(0xffffffffu, sc, 1);
                    sc += __shfl_xor_sync(0xffffffffu, sc, 2);
                    sc += __shfl_xor_sync(0xffffffffu, sc, 4);
                    float p = __expf(sc);
                    p = (b + j < cnt) ? p : 0.f;
                    uint2 vraw = *(const uint2*)(Vb + (off >> 1));
                    float2 va = __half22float2(*reinterpret_cast<const __half2*>(&vraw.x));
                    float2 vb = __half22float2(*reinterpret_cast<const __half2*>(&vraw.y));
                    d += p;
                    acc.x = fmaf(p, va.x, acc.x);
                    acc.y = fmaf(p, va.y, acc.y);
                    acc.z = fmaf(p, vb.x, acc.z);
                    acc.w = fmaf(p, vb.y, acc.w);
                }
            }
        }
    }

    float inv = (d > 0.f) ? (1.f / d) : 0.f;
    float4 o = make_float4(acc.x * inv, acc.y * inv, acc.z * inv, acc.w * inv);
    *(float4*)&out[(long)gw * DD + lane * 4] = o;
}

// ---------------- launch: fork-join overlap of proj with CSR chain ----------
extern "C" void kernel_launch(void* const* d_in, const int* in_sizes, int n_in,
                              void* d_out, int out_size) {
    const float* x  = (const float*)d_in[0];
    const float* Wk = (const float*)d_in[1];
    const float* bk = (const float*)d_in[2];
    const float* Wq = (const float*)d_in[3];
    const float* bq = (const float*)d_in[4];
    const float* Wv = (const float*)d_in[5];
    const float* bv = (const float*)d_in[6];
    const int*  src = (const int*)d_in[7];
    const int*  dst = (const int*)d_in[8];
    float* out = (float*)d_out;

    int n = in_sizes[0] / DD;   // 50000
    int E = in_sizes[7];        // 1600000

    cudaStream_t s2;
    cudaStreamCreateWithFlags(&s2, cudaStreamNonBlocking);
    cudaEvent_t evF, evJ;
    cudaEventCreateWithFlags(&evF, cudaEventDisableTiming);
    cudaEventCreateWithFlags(&evJ, cudaEventDisableTiming);

    cudaFuncSetAttribute(proj_wmma, cudaFuncAttributeMaxDynamicSharedMemorySize,
                         PS_TOT);

    int prepN = (n > 3 * DD * DD) ? n : 3 * DD * DD;
    prep_w<<<(prepN + 255) / 256, 256>>>(Wk, Wq, Wv, n);     // stream 0

    // fork: proj on s2 (needs prep's W split); CSR chain stays on stream 0
    cudaEventRecord(evF, 0);
    cudaStreamWaitEvent(s2, evF, 0);
    dim3 pg((n + 63) / 64, 3);
    proj_wmma<<<pg, 256, PS_TOT, s2>>>(x, bk, bq, bv, n);

    hist_kernel<<<(E + 1023) / 1024, 256>>>(dst, E);
    scan_chain_kernel<<<(n + 1023) / 1024, 1024>>>(n);
    fill_kernel<<<(E + 1023) / 1024, 256>>>(src, dst, E);

    // join: aggregate needs both branches
    cudaEventRecord(evJ, s2);
    cudaStreamWaitEvent(0, evJ, 0);

    int totalThreads = n * 32;
    aggregate_kernel<<<(totalThreads + 255) / 256, 256>>>(out, n);
}

// round 17
// speedup vs baseline: 1.2135x; 1.0467x over previous
#include <cuda_runtime.h>
#include <cuda_fp16.h>
#include <mma.h>
#include <math_constants.h>
#include <cstdint>

using namespace nvcuda;

#define DD   128
#define MAXN 50048
#define MAXE 1600256

// ---------------- device scratch (no allocations allowed) ----------------
__device__ __align__(128) __half g_Kh[MAXN * DD];
__device__ __align__(128) float  g_Q [MAXN * DD];
__device__ __align__(128) __half g_Vh[MAXN * DD];
__device__ __align__(128) __half g_Whi[3 * DD * DD];
__device__ __align__(128) __half g_Wlo[3 * DD * DD];
__device__ int g_deg[MAXN];
__device__ int g_off[MAXN + 1];
__device__ int g_pos[MAXN];
__device__ int g_esrc[MAXE];        // BYTE offsets (src * 256; valid for K and V)
__device__ int g_chain[64];

// ---------------- prep: split W hi/lo + zero g_deg + chain flags ------------
__global__ void prep_w(const float* __restrict__ Wk,
                       const float* __restrict__ Wq,
                       const float* __restrict__ Wv, int n) {
    int idx = blockIdx.x * blockDim.x + threadIdx.x;
    if (idx < 64) g_chain[idx] = 0;
    if (idx < n) g_deg[idx] = 0;
    if (idx >= 3 * DD * DD) return;
    int which = idx / (DD * DD);
    int i     = idx - which * (DD * DD);
    const float* W = (which == 0) ? Wk : (which == 1) ? Wq : Wv;
    float v  = W[i];
    __half h = __float2half_rn(v);
    __half l = __float2half_rn(v - __half2float(h));
    g_Whi[idx] = h;
    g_Wlo[idx] = l;
}

// ---------------- projection via wmma, 2 CTAs/SM ----------------------------
#define LDH  136
#define LDO  132
#define SA_BYTES  (64 * LDH * 2)
#define SB_BYTES  (128 * LDH * 2)
#define PS_AHI    0
#define PS_ALO    (SA_BYTES)
#define PS_BHI    (2 * SA_BYTES)
#define PS_BLO    (2 * SA_BYTES + SB_BYTES)
#define PS_TOT    (2 * SA_BYTES + 2 * SB_BYTES)

__global__ void __launch_bounds__(256, 2)
proj_wmma(const float* __restrict__ X,
          const float* __restrict__ bk,
          const float* __restrict__ bq,
          const float* __restrict__ bv,
          int n) {
    extern __shared__ char smem[];
    __half* sAhi = (__half*)(smem + PS_AHI);
    __half* sAlo = (__half*)(smem + PS_ALO);
    __half* sBhi = (__half*)(smem + PS_BHI);
    __half* sBlo = (__half*)(smem + PS_BLO);
    float*  sOut = (float*)(smem);

    const int tid = threadIdx.x, wid = tid >> 5;
    const int wr = wid >> 2, wc = wid & 3;
    const int which = blockIdx.y;
    const int m0 = blockIdx.x * 64;

    for (int idx = tid; idx < 64 * 32; idx += 256) {
        int row = idx >> 5;
        int c0  = (idx & 31) << 2;
        int gr  = m0 + row;
        float4 v = (gr < n) ? *(const float4*)&X[(long)gr * DD + c0]
                            : make_float4(0.f, 0.f, 0.f, 0.f);
        __half h0 = __float2half_rn(v.x), h1 = __float2half_rn(v.y);
        __half h2 = __float2half_rn(v.z), h3 = __float2half_rn(v.w);
        __half l0 = __float2half_rn(v.x - __half2float(h0));
        __half l1 = __float2half_rn(v.y - __half2float(h1));
        __half l2 = __float2half_rn(v.z - __half2float(h2));
        __half l3 = __float2half_rn(v.w - __half2float(h3));
        __half2 H01 = __halves2half2(h0, h1), H23 = __halves2half2(h2, h3);
        __half2 L01 = __halves2half2(l0, l1), L23 = __halves2half2(l2, l3);
        uint2 uh; uh.x = *(uint32_t*)&H01; uh.y = *(uint32_t*)&H23;
        uint2 ul; ul.x = *(uint32_t*)&L01; ul.y = *(uint32_t*)&L23;
        *(uint2*)&sAhi[row * LDH + c0] = uh;
        *(uint2*)&sAlo[row * LDH + c0] = ul;
    }

    {
        const uint4* ghi = (const uint4*)(g_Whi + which * (DD * DD));
        const uint4* glo = (const uint4*)(g_Wlo + which * (DD * DD));
        for (int idx = tid; idx < 128 * 16; idx += 256) {
            int c  = idx >> 4;
            int kq = (idx & 15) << 3;
            uint4 vh = ghi[idx];
            uint4 vl = glo[idx];
            *(uint4*)&sBhi[c * LDH + kq] = vh;
            *(uint4*)&sBlo[c * LDH + kq] = vl;
        }
    }
    __syncthreads();

    wmma::fragment<wmma::accumulator, 16, 16, 16, float> acc[2][2];
#pragma unroll
    for (int i = 0; i < 2; i++)
#pragma unroll
        for (int j = 0; j < 2; j++) wmma::fill_fragment(acc[i][j], 0.f);

#pragma unroll
    for (int k0 = 0; k0 < 128; k0 += 16) {
        wmma::fragment<wmma::matrix_a, 16, 16, 16, __half, wmma::row_major> ah[2], al[2];
#pragma unroll
        for (int i = 0; i < 2; i++) {
            wmma::load_matrix_sync(ah[i], sAhi + (wr * 32 + i * 16) * LDH + k0, LDH);
            wmma::load_matrix_sync(al[i], sAlo + (wr * 32 + i * 16) * LDH + k0, LDH);
        }
#pragma unroll
        for (int j = 0; j < 2; j++) {
            wmma::fragment<wmma::matrix_b, 16, 16, 16, __half, wmma::col_major> bh, bl;
            wmma::load_matrix_sync(bh, sBhi + (wc * 32 + j * 16) * LDH + k0, LDH);
            wmma::load_matrix_sync(bl, sBlo + (wc * 32 + j * 16) * LDH + k0, LDH);
#pragma unroll
            for (int i = 0; i < 2; i++) {
                wmma::mma_sync(acc[i][j], ah[i], bh, acc[i][j]);
                wmma::mma_sync(acc[i][j], ah[i], bl, acc[i][j]);
                wmma::mma_sync(acc[i][j], al[i], bh, acc[i][j]);
            }
        }
    }

    __syncthreads();
#pragma unroll
    for (int i = 0; i < 2; i++)
#pragma unroll
        for (int j = 0; j < 2; j++)
            wmma::store_matrix_sync(&sOut[(wr * 32 + i * 16) * LDO + wc * 32 + j * 16],
                                    acc[i][j], LDO, wmma::mem_row_major);
    __syncthreads();

    const float* b = (which == 0) ? bk : (which == 1) ? bq : bv;
    for (int idx = tid; idx < 64 * 32; idx += 256) {
        int row = idx >> 5;
        int c0  = (idx & 31) << 2;
        int gr  = m0 + row;
        if (gr < n) {
            float4 o  = *(const float4*)&sOut[row * LDO + c0];
            float4 bb = *(const float4*)&b[c0];
            o.x += bb.x; o.y += bb.y; o.z += bb.z; o.w += bb.w;
            if (which == 1) {
                *(float4*)&g_Q[(long)gr * DD + c0] = o;
            } else {
                __half* Yh = (which == 0) ? g_Kh : g_Vh;
                __half2 h01 = __halves2half2(__float2half_rn(o.x), __float2half_rn(o.y));
                __half2 h23 = __halves2half2(__float2half_rn(o.z), __float2half_rn(o.w));
                uint2 u; u.x = *(uint32_t*)&h01; u.y = *(uint32_t*)&h23;
                *(uint2*)&Yh[(long)gr * DD + c0] = u;
            }
        }
    }
}

// ---------------- CSR build (unchanged) --------------------------------------
__global__ void hist_kernel(const int* __restrict__ dst, int E) {
    int base = blockIdx.x * 1024 + threadIdx.x;
#pragma unroll
    for (int i = 0; i < 4; i++) {
        int e = base + i * 256;
        if (e < E) atomicAdd(&g_deg[dst[e]], 1);
    }
}

__global__ void __launch_bounds__(1024, 1)
scan_chain_kernel(int n) {
    __shared__ int wsum[32];
    __shared__ int s_total, s_prefix;

    const int tid  = threadIdx.x;
    const int lane = tid & 31, warp = tid >> 5;
    const int i    = blockIdx.x * 1024 + tid;

    int v = (i < n) ? g_deg[i] : 0;

    int inc = v;
#pragma unroll
    for (int o = 1; o < 32; o <<= 1) {
        int t = __shfl_up_sync(0xffffffffu, inc, o);
        if (lane >= o) inc += t;
    }
    if (lane == 31) wsum[warp] = inc;
    __syncthreads();

    if (warp == 0) {
        int w  = wsum[lane];
        int wi = w;
#pragma unroll
        for (int o = 1; o < 32; o <<= 1) {
            int t = __shfl_up_sync(0xffffffffu, wi, o);
            if (lane >= o) wi += t;
        }
        wsum[lane] = wi - w;
        if (lane == 31) s_total = wi;
    }
    __syncthreads();

    const int excl = (inc - v) + wsum[warp];

    if (tid == 0) {
        int prefix = 0;
        if (blockIdx.x > 0) {
            int f;
            do { f = atomicAdd(&g_chain[blockIdx.x - 1], 0); } while (f == 0);
            prefix = f - 1;
        }
        atomicExch(&g_chain[blockIdx.x], prefix + s_total + 1);
        s_prefix = prefix;
    }
    __syncthreads();

    if (i < n) {
        int o = s_prefix + excl;
        g_off[i] = o;
        g_pos[i] = o;
    }
    if (blockIdx.x == gridDim.x - 1 && tid == 0)
        g_off[n] = s_prefix + s_total;
}

__global__ void fill_kernel(const int* __restrict__ src,
                            const int* __restrict__ dst, int E) {
    int base = blockIdx.x * 1024 + threadIdx.x;
#pragma unroll
    for (int i = 0; i < 4; i++) {
        int e = base + i * 256;
        if (e < E) {
            int p = atomicAdd(&g_pos[dst[e]], 1);
            g_esrc[p] = src[e] << 8;     // byte offset (fp16 rows, 256 B)
        }
    }
}

// ---------------- fused edge-softmax + aggregate -----------------------------
// K and V both fp16, 256B rows -> ONE offset serves both. cnt==32 fast path.
__global__ void __launch_bounds__(256, 6)
aggregate_kernel(float* __restrict__ out, int n) {
    int gw   = (blockIdx.x * blockDim.x + threadIdx.x) >> 5;
    int lane = threadIdx.x & 31;
    if (gw >= n) return;

    const int beg = g_off[gw];
    const int end = g_off[gw + 1];

    const char* Kb = (const char*)g_Kh + lane * 8;
    const char* Vb = (const char*)g_Vh + lane * 8;
    const float4 q4 = *(const float4*)&g_Q[(long)gw * DD + lane * 4];

    float  d = 0.f;
    float4 acc = make_float4(0.f, 0.f, 0.f, 0.f);

    for (int e0 = beg; e0 < end; e0 += 32) {
        if (end - e0 >= 32) {
            int myoff = g_esrc[e0 + lane];
#pragma unroll
            for (int b = 0; b < 32; b += 8) {
#pragma unroll
                for (int j = 0; j < 8; j++) {
                    int off = __shfl_sync(0xffffffffu, myoff, b + j);
                    uint2 kraw = *(const uint2*)(Kb + off);
                    float2 ka = __half22float2(*reinterpret_cast<const __half2*>(&kraw.x));
                    float2 kb = __half22float2(*reinterpret_cast<const __half2*>(&kraw.y));
                    float sc = ka.x * q4.x + ka.y * q4.y + kb.x * q4.z + kb.y * q4.w;
                    sc += __shfl_xor_sync(0xffffffffu, sc, 1);
                    sc += __shfl_xor_sync(0xffffffffu, sc, 2);
                    sc += __shfl_xor_sync(0xffffffffu, sc, 4);
                    float p = __expf(sc);
                    uint2 vraw = *(const uint2*)(Vb + off);
                    float2 va = __half22float2(*reinterpret_cast<const __half2*>(&vraw.x));
                    float2 vb = __half22float2(*reinterpret_cast<const __half2*>(&vraw.y));
                    d += p;
                    acc.x = fmaf(p, va.x, acc.x);
                    acc.y = fmaf(p, va.y, acc.y);
                    acc.z = fmaf(p, vb.x, acc.z);
                    acc.w = fmaf(p, vb.y, acc.w);
                }
            }
        } else {
            int cnt   = end - e0;
            int myoff = (e0 + lane < end) ? g_esrc[e0 + lane] : 0;
            for (int b = 0; b < cnt; b += 8) {
#pragma unroll
                for (int j = 0; j < 8; j++) {
                    int off = __shfl_sync(0xffffffffu, myoff, b + j);
                    uint2 kraw = *(const uint2*)(Kb + off);
                    float2 ka = __half22float2(*reinterpret_cast<const __half2*>(&kraw.x));
                    float2 kb = __half22float2(*reinterpret_cast<const __half2*>(&kraw.y));
                    float sc = ka.x * q4.x + ka.y * q4.y + kb.x * q4.z + kb.y * q4.w;
                    sc += __shfl_xor_sync(0xffffffffu, sc, 1);
                    sc += __shfl_xor_sync(0xffffffffu, sc, 2);
                    sc += __shfl_xor_sync(0xffffffffu, sc, 4);
                    float p = __expf(sc);
                    p = (b + j < cnt) ? p : 0.f;
                    uint2 vraw = *(const uint2*)(Vb + off);
                    float2 va = __half22float2(*reinterpret_cast<const __half2*>(&vraw.x));
                    float2 vb = __half22float2(*reinterpret_cast<const __half2*>(&vraw.y));
                    d += p;
                    acc.x = fmaf(p, va.x, acc.x);
                    acc.y = fmaf(p, va.y, acc.y);
                    acc.z = fmaf(p, vb.x, acc.z);
                    acc.w = fmaf(p, vb.y, acc.w);
                }
            }
        }
    }

    float inv = (d > 0.f) ? (1.f / d) : 0.f;
    float4 o = make_float4(acc.x * inv, acc.y * inv, acc.z * inv, acc.w * inv);
    *(float4*)&out[(long)gw * DD + lane * 4] = o;
}

// ---------------- launch: fork-join overlap of proj with CSR chain ----------
extern "C" void kernel_launch(void* const* d_in, const int* in_sizes, int n_in,
                              void* d_out, int out_size) {
    const float* x  = (const float*)d_in[0];
    const float* Wk = (const float*)d_in[1];
    const float* bk = (const float*)d_in[2];
    const float* Wq = (const float*)d_in[3];
    const float* bq = (const float*)d_in[4];
    const float* Wv = (const float*)d_in[5];
    const float* bv = (const float*)d_in[6];
    const int*  src = (const int*)d_in[7];
    const int*  dst = (const int*)d_in[8];
    float* out = (float*)d_out;

    int n = in_sizes[0] / DD;   // 50000
    int E = in_sizes[7];        // 1600000

    cudaStream_t s2;
    cudaStreamCreateWithFlags(&s2, cudaStreamNonBlocking);
    cudaEvent_t evF, evJ;
    cudaEventCreateWithFlags(&evF, cudaEventDisableTiming);
    cudaEventCreateWithFlags(&evJ, cudaEventDisableTiming);

    cudaFuncSetAttribute(proj_wmma, cudaFuncAttributeMaxDynamicSharedMemorySize,
                         PS_TOT);

    int prepN = (n > 3 * DD * DD) ? n : 3 * DD * DD;
    prep_w<<<(prepN + 255) / 256, 256>>>(Wk, Wq, Wv, n);     // stream 0

    // fork: proj on s2 (needs prep's W split); CSR chain stays on stream 0
    cudaEventRecord(evF, 0);
    cudaStreamWaitEvent(s2, evF, 0);
    dim3 pg((n + 63) / 64, 3);
    proj_wmma<<<pg, 256, PS_TOT, s2>>>(x, bk, bq, bv, n);

    hist_kernel<<<(E + 1023) / 1024, 256>>>(dst, E);
    scan_chain_kernel<<<(n + 1023) / 1024, 1024>>>(n);
    fill_kernel<<<(E + 1023) / 1024, 256>>>(src, dst, E);

    // join: aggregate needs both branches
    cudaEventRecord(evJ, s2);
    cudaStreamWaitEvent(0, evJ, 0);

    int totalThreads = n * 32;
    aggregate_kernel<<<(totalThreads + 255) / 256, 256>>>(out, n);
}